// round 14
// baseline (speedup 1.0000x reference)
#include <cuda_runtime.h>
#include <cuda_fp16.h>
#include <math.h>
#include <stdint.h>

#define B    8
#define CIN  512
#define COUT 256
#define H    64
#define W    64

// ---------------- static device scratch (16B-aligned for cp.async) ----------
__device__ __align__(16) float  g_s[B * CIN];
__device__ __align__(16) float  g_qT[CIN * COUT];           // q[ci][co] = sum_k w^2
__device__ __align__(16) float  g_demod[B * COUT];
__device__ __align__(16) __half g_wtT[9 * COUT * CIN];      // [tap][co][ci]
__device__ __align__(16) __half g_xsT[B * 66 * 66 * CIN];   // zero halo [b][y+1][x+1][ci]
__device__ __align__(16) __half g_midp[4][B * COUT * 65 * 68];  // parity planes

__device__ __forceinline__ uint32_t smem_u32(const void* p) {
    uint32_t a;
    asm("{ .reg .u64 t; cvta.to.shared.u64 t, %1; cvt.u32.u64 %0, t; }"
        : "=r"(a) : "l"(p));
    return a;
}
__device__ __forceinline__ uint32_t sw128(uint32_t o) { return o ^ ((o >> 3) & 0x70); }

#define CP_ASYNC16(dst, src) \
    asm volatile("cp.async.cg.shared.global [%0], [%1], 16;" \
                 :: "r"(dst), "l"(src) : "memory")
#define CP_COMMIT() asm volatile("cp.async.commit_group;" ::: "memory")
#define CP_WAIT1()  asm volatile("cp.async.wait_group 1;" ::: "memory")
#define CP_WAIT0()  asm volatile("cp.async.wait_group 0;" ::: "memory")

// ---------------------------------------------------------------------------
// Kernel 0: g_qT[ci][co] = sum_k weight[co][ci][k]^2
// ---------------------------------------------------------------------------
__global__ void k_qT(const float* __restrict__ weight) {
    int co = blockIdx.x;
    __shared__ float sw[CIN * 9];
    for (int e = threadIdx.x; e < CIN * 9; e += 256) sw[e] = weight[co * CIN * 9 + e];
    __syncthreads();
    for (int ci = threadIdx.x; ci < CIN; ci += 256) {
        float q = 0.f;
#pragma unroll
        for (int k = 0; k < 9; k++) { float w = sw[ci * 9 + k]; q += w * w; }
        g_qT[ci * COUT + co] = q;
    }
}

// ---------------------------------------------------------------------------
// Kernel 1: fused style-dot + demod (one block per batch, 512 threads)
// s[b][ci] = style[b]·modW[ci]/sqrt(512) + bias[ci]
// demod[b][co] = rsqrt(sc2 * sum_ci qT[ci][co]*s^2 + 1e-8)
// ---------------------------------------------------------------------------
__global__ void __launch_bounds__(512) k_style_demod(
        const float* __restrict__ style,
        const float* __restrict__ modw,
        const float* __restrict__ modb) {
    int b = blockIdx.x;
    int tid = threadIdx.x;  // = ci
    __shared__ __align__(16) float ss[CIN];
    __shared__ float s2[CIN];
    ss[tid] = style[b * CIN + tid];
    __syncthreads();
    const float4* row = reinterpret_cast<const float4*>(modw + tid * CIN);
    const float4* s4p = reinterpret_cast<const float4*>(ss);
    float acc = 0.f;
#pragma unroll 4
    for (int k = 0; k < CIN / 4; k++) {
        float4 m = row[k];
        float4 s4 = s4p[k];
        acc += m.x * s4.x + m.y * s4.y + m.z * s4.z + m.w * s4.w;
    }
    float s = acc * 0.044194173824159216f + modb[tid];
    g_s[b * CIN + tid] = s;
    s2[tid] = s * s;
    __syncthreads();
    if (tid < COUT) {
        float q = 0.f;
#pragma unroll 8
        for (int ci = 0; ci < CIN; ci++)
            q += g_qT[ci * COUT + tid] * s2[ci];
        const float sc2 = 0.014731391274719739f * 0.014731391274719739f;
        g_demod[b * COUT + tid] = rsqrtf(sc2 * q + 1e-8f);
    }
}

// ---------------------------------------------------------------------------
// Kernel 2: merged prep — wtT (bx<256) | halo (bx<2336) | xsT slices (rest)
// ---------------------------------------------------------------------------
__global__ void k_prep(const float* __restrict__ weight,
                       const float* __restrict__ x) {
    __shared__ __align__(16) char sbuf[CIN * 9 * 4];  // 18432 B, reused
    int bx = blockIdx.x, tid = threadIdx.x;

    if (bx < 256) {
        // ---- wtT: g_wtT[tap][co][ci] = half(scale * weight[co][ci][tap])
        int co = bx;
        float* sw = reinterpret_cast<float*>(sbuf);
        for (int e = tid; e < CIN * 9; e += 256) sw[e] = weight[co * CIN * 9 + e];
        __syncthreads();
        for (int e = tid; e < CIN * 9; e += 256) {
            int tap = e >> 9, ci = e & 511;
            g_wtT[(tap * COUT + co) * CIN + ci] =
                __float2half_rn(0.014731391274719739f * sw[ci * 9 + tap]);
        }
    } else if (bx < 2336) {
        // ---- halo: zero y1 in {0,65} or x1 in {0,65}
        int e = bx - 256;
        int b = e / 260, px = e - b * 260;
        int y1, x1;
        if (px < 66)       { y1 = 0;  x1 = px; }
        else if (px < 132) { y1 = 65; x1 = px - 66; }
        else if (px < 196) { y1 = px - 132 + 1; x1 = 0; }
        else               { y1 = px - 196 + 1; x1 = 65; }
        reinterpret_cast<__half2*>(
            g_xsT + ((size_t)(b * 66 + y1) * 66 + x1) * CIN)[tid] =
            __floats2half2_rn(0.f, 0.f);
    } else {
        // ---- xsT: one 32ci x 64x transpose chunk per block
        int e = bx - 2336;
        int y = e & 63, b = (e >> 6) & 7, ci0 = (e >> 9) * 32;
        float (*t)[65] = reinterpret_cast<float (*)[65]>(sbuf);
        const float* xb = x + (size_t)b * CIN * H * W + y * W;
        __half* ob = g_xsT + ((size_t)(b * 66 + y + 1) * 66 + 1) * CIN;
#pragma unroll
        for (int k = 0; k < 8; k++) {
            int f = tid + k * 256;
            int ci = f >> 6, xc = f & 63;
            float s = g_s[b * CIN + ci0 + ci];
            t[ci][xc] = xb[(ci0 + ci) * H * W + xc] * s;
        }
        __syncthreads();
#pragma unroll
        for (int k = 0; k < 4; k++) {
            int f = tid + k * 256;
            int xc = f >> 4, cp = f & 15;
            __half2 h = __floats2half2_rn(t[cp * 2][xc], t[cp * 2 + 1][xc]);
            *(reinterpret_cast<__half2*>(ob + (size_t)xc * CIN + ci0) + cp) = h;
        }
    }
}

// ---------------------------------------------------------------------------
// Kernel 3: conv (round-13 proven config): all four parities, one launch.
// CTA: 128 co x 128 px, 256 threads, 2 CTA/SM, 3-stage cp.async pipeline.
// ---------------------------------------------------------------------------
#define SM_US   0
#define SM_VS   512
#define SM_UE   1024
#define SM_BUF  2048
#define SM_DYN  100352

__global__ void __launch_bounds__(256, 2) k_conv() {
    extern __shared__ __align__(1024) char smem[];
    const uint32_t sb = smem_u32(smem);
    int* us = (int*)(smem + SM_US);
    int* vs = (int*)(smem + SM_VS);
    int* ue = (int*)(smem + SM_UE);

    const int tid = threadIdx.x;
    const int lane = tid & 31, warp = tid >> 5;
    const int g = lane >> 2, tg = lane & 3;
    const int wm = warp >> 1, wn = warp & 1;
    const int cobase = blockIdx.y * 128;
    const int b = blockIdx.z;

    int bx = blockIdx.x;
    int py, px, xt;
    if (bx < 34)       { py = 0; px = 0; xt = bx; }
    else if (bx < 67)  { py = 0; px = 1; xt = bx - 34; }
    else if (bx < 100) { py = 1; px = 0; xt = bx - 67; }
    else               { py = 1; px = 1; xt = bx - 100; }
    const int U = 65 - py, V = 65 - px;
    const int NPIX = U * V;
    const int nky = 2 - py, nkx = 2 - px;
    const int NC = nky * nkx * 8;
    const int n0 = xt * 128;

    {
        int p = n0 + tid;
        int u = p / V, v = p - u * V;
        bool ok = (p < NPIX);
        if (tid < 128) {
            us[tid] = ok ? u : 0;
            vs[tid] = ok ? v : 0;
            ue[tid] = ok ? u : -1;
        }
    }
    __syncthreads();

    const __half* xb = g_xsT + (size_t)b * 66 * 66 * CIN;

    auto issue = [&](int gidx) {
        const int t = gidx >> 3;
        const int ci0 = (gidx & 7) * 64;
        const int iy = (nkx == 2) ? (t >> 1) : t;
        const int ix = t - iy * nkx;
        const int ky = (py == 0) ? iy * 2 : 1;
        const int kx = (px == 0) ? ix * 2 : 1;
        const int dy = (py == 0) ? iy : 0;
        const int dx = (px == 0) ? ix : 0;
        const int bufi = gidx - (gidx / 3) * 3;
        const uint32_t Ab = sb + SM_BUF + bufi * 32768;
        const uint32_t Bb = Ab + 16384;
        const __half* wt = g_wtT + (ky * 3 + kx) * COUT * CIN + ci0;
#pragma unroll
        for (int k = 0; k < 4; k++) {
            int f = tid + k * 256;
            int co = f >> 3, q = f & 7;
            const __half* src = wt + (size_t)(cobase + co) * CIN + q * 8;
            CP_ASYNC16(Ab + sw128(co * 128 + q * 16), src);
        }
#pragma unroll
        for (int k = 0; k < 4; k++) {
            int f = tid + k * 256;
            int j = f >> 3, q = f & 7;
            int y1 = us[j] + 1 - dy, x1 = vs[j] + 1 - dx;
            const __half* src = xb + ((size_t)(y1 * 66 + x1)) * CIN + ci0 + q * 8;
            CP_ASYNC16(Bb + sw128(j * 128 + q * 16), src);
        }
        CP_COMMIT();
    };

    float acc[2][8][4];
#pragma unroll
    for (int mi = 0; mi < 2; mi++)
#pragma unroll
        for (int nt = 0; nt < 8; nt++)
#pragma unroll
            for (int r = 0; r < 4; r++) acc[mi][nt][r] = 0.f;

    issue(0);
    issue(1);

    const int arow = wm * 32 + (lane & 15);
    const int acolb = (lane >> 4) * 16;
    const int brow = wn * 64 + ((lane >> 4) << 3) + (lane & 7);
    const int bcolb = ((lane >> 3) & 1) * 16;

#pragma unroll 1
    for (int c = 0; c < NC; c++) {
        if (c == NC - 1) { CP_WAIT0(); } else { CP_WAIT1(); }
        __syncthreads();
        if (c + 2 < NC) issue(c + 2);
        const int bufi = c - (c / 3) * 3;
        const uint32_t Ab = sb + SM_BUF + bufi * 32768;
        const uint32_t Bb = Ab + 16384;
#pragma unroll
        for (int ks = 0; ks < 4; ks++) {
            uint32_t a[2][4], bb[8][2];
#pragma unroll
            for (int mi = 0; mi < 2; mi++) {
                uint32_t addr = Ab + sw128((arow + mi * 16) * 128 + acolb + ks * 32);
                asm volatile(
                    "ldmatrix.sync.aligned.m8n8.x4.shared.b16 {%0,%1,%2,%3}, [%4];"
                    : "=r"(a[mi][0]), "=r"(a[mi][1]), "=r"(a[mi][2]), "=r"(a[mi][3])
                    : "r"(addr) : "memory");
            }
#pragma unroll
            for (int ntp = 0; ntp < 4; ntp++) {
                uint32_t addr = Bb + sw128((brow + ntp * 16) * 128 + bcolb + ks * 32);
                uint32_t r0, r1, r2, r3;
                asm volatile(
                    "ldmatrix.sync.aligned.m8n8.x4.shared.b16 {%0,%1,%2,%3}, [%4];"
                    : "=r"(r0), "=r"(r1), "=r"(r2), "=r"(r3)
                    : "r"(addr) : "memory");
                bb[ntp * 2][0] = r0;     bb[ntp * 2][1] = r1;
                bb[ntp * 2 + 1][0] = r2; bb[ntp * 2 + 1][1] = r3;
            }
#pragma unroll
            for (int mi = 0; mi < 2; mi++)
#pragma unroll
                for (int nt = 0; nt < 8; nt++) {
                    asm volatile(
                        "mma.sync.aligned.m16n8k16.row.col.f32.f16.f16.f32 "
                        "{%0,%1,%2,%3}, {%4,%5,%6,%7}, {%8,%9}, {%0,%1,%2,%3};"
                        : "+f"(acc[mi][nt][0]), "+f"(acc[mi][nt][1]),
                          "+f"(acc[mi][nt][2]), "+f"(acc[mi][nt][3])
                        : "r"(a[mi][0]), "r"(a[mi][1]), "r"(a[mi][2]),
                          "r"(a[mi][3]), "r"(bb[nt][0]), "r"(bb[nt][1]));
                }
        }
    }

    __half* plane = g_midp[py * 2 + px];
#pragma unroll
    for (int mi = 0; mi < 2; mi++) {
        int r0 = cobase + wm * 32 + mi * 16 + g;
        float d0 = g_demod[b * COUT + r0];
        float d1 = g_demod[b * COUT + r0 + 8];
        __half* p0 = plane + (size_t)(b * COUT + r0) * 65 * 68;
        __half* p1 = plane + (size_t)(b * COUT + r0 + 8) * 65 * 68;
#pragma unroll
        for (int nt = 0; nt < 8; nt++) {
            int j = wn * 64 + nt * 8 + tg * 2;
            int u0 = ue[j], u1 = ue[j + 1];
            int v0 = vs[j], v1 = vs[j + 1];
            if (u0 >= 0 && u1 == u0 && v1 == v0 + 1 && (v0 & 1) == 0) {
                __half2 h0 = __floats2half2_rn(acc[mi][nt][0] * d0,
                                               acc[mi][nt][1] * d0);
                __half2 h1 = __floats2half2_rn(acc[mi][nt][2] * d1,
                                               acc[mi][nt][3] * d1);
                *reinterpret_cast<__half2*>(p0 + u0 * 68 + v0) = h0;
                *reinterpret_cast<__half2*>(p1 + u0 * 68 + v0) = h1;
            } else {
                if (u0 >= 0) {
                    p0[u0 * 68 + v0] = __float2half_rn(acc[mi][nt][0] * d0);
                    p1[u0 * 68 + v0] = __float2half_rn(acc[mi][nt][2] * d1);
                }
                if (u1 >= 0) {
                    p0[u1 * 68 + v1] = __float2half_rn(acc[mi][nt][1] * d0);
                    p1[u1 * 68 + v1] = __float2half_rn(acc[mi][nt][3] * d1);
                }
            }
        }
    }
}

// ---------------------------------------------------------------------------
// Kernel 4: plane-resident blur (round-13 proven)
// ---------------------------------------------------------------------------
#define PLN 4420  // 65*68 halves per plane

__global__ void __launch_bounds__(256) k_blur(float* __restrict__ out) {
    int bc = blockIdx.x;
    __shared__ __align__(16) __half sm[8 + 4 * PLN];
    const int tid = threadIdx.x;

    for (int e = tid; e < 4 * 65 * 17; e += 256) {
        int p = e / (65 * 17);
        int rem = e - p * 65 * 17;
        int r = rem / 17, c4 = rem - r * 17;
        uint2 val = *reinterpret_cast<const uint2*>(
            g_midp[p] + (size_t)bc * PLN + r * 68 + c4 * 4);
        *reinterpret_cast<uint2*>(sm + 8 + p * PLN + r * 68 + c4 * 4) = val;
    }
    if (tid < 8) sm[tid] = __float2half(0.f);
    __syncthreads();
#pragma unroll
    for (int p = 0; p < 4; p++) {
        int Vp = 65 - (p & 1);
        int nc = 68 - Vp;
        for (int e = tid; e < 65 * nc; e += 256) {
            int rr = e / nc, cc = e - rr * nc;
            sm[8 + p * PLN + rr * 68 + Vp + cc] = __float2half(0.f);
        }
        if (p >> 1) {
            for (int e = tid; e < 68; e += 256)
                sm[8 + p * PLN + 64 * 68 + e] = __float2half(0.f);
        }
    }
    __syncthreads();

    const int X = tid & 127, uh = tid >> 7;
    const int v = X >> 1, cpar = X & 1;
    const __half* sp = sm + 8;

    auto HS = [&](int my) -> float {
        int pyb = my & 1, r = my >> 1;
        const __half* E = sp + (pyb * 2) * PLN + r * 68;
        const __half* O = sp + (pyb * 2 + 1) * PLN + r * 68;
        if (cpar == 0)
            return __half2float(O[v - 1]) + 3.f * __half2float(E[v]) +
                   3.f * __half2float(O[v]) + __half2float(E[v + 1]);
        else
            return __half2float(E[v]) + 3.f * __half2float(O[v]) +
                   3.f * __half2float(E[v + 1]) + __half2float(O[v + 1]);
    };

    const int u0 = uh * 32;
    float hsOprev = (u0 == 0) ? 0.f : HS(2 * u0 - 1);
    float hsEc = HS(2 * u0);
    float hsOc = HS(2 * u0 + 1);
    float* ob = out + (size_t)bc * 128 * 128 + X;
#pragma unroll 4
    for (int u = u0; u < u0 + 32; u++) {
        float hsEn = HS(2 * u + 2);
        float hsOn = HS(2 * u + 3);
        ob[(2 * u) * 128] =
            (hsOprev + 3.f * hsEc + 3.f * hsOc + hsEn) * (1.f / 16.f);
        ob[(2 * u + 1) * 128] =
            (hsEc + 3.f * hsOc + 3.f * hsEn + hsOn) * (1.f / 16.f);
        hsOprev = hsOc; hsEc = hsEn; hsOc = hsOn;
    }
}

// ---------------------------------------------------------------------------
extern "C" void kernel_launch(void* const* d_in, const int* in_sizes, int n_in,
                              void* d_out, int out_size) {
    const float* input  = (const float*)d_in[0];
    const float* style  = (const float*)d_in[1];
    const float* weight = (const float*)d_in[2];
    const float* modw   = (const float*)d_in[3];
    const float* modb   = (const float*)d_in[4];
    float* out = (float*)d_out;

    cudaFuncSetAttribute(k_conv, cudaFuncAttributeMaxDynamicSharedMemorySize, SM_DYN);

    k_qT<<<COUT, 256>>>(weight);
    k_style_demod<<<B, 512>>>(style, modw, modb);
    k_prep<<<256 + 2080 + 8192, 256>>>(weight, input);
    k_conv<<<dim3(132, 2, B), 256, SM_DYN>>>();
    k_blur<<<B * COUT, 256>>>(out);
}

// round 15
// speedup vs baseline: 1.0588x; 1.0588x over previous
#include <cuda_runtime.h>
#include <cuda_fp16.h>
#include <math.h>
#include <stdint.h>

#define B    8
#define CIN  512
#define COUT 256
#define H    64
#define W    64

// ---------------- static device scratch (16B-aligned for cp.async) ----------
__device__ __align__(16) float  g_s[B * CIN];
__device__ __align__(16) float  g_demod[B * COUT];
__device__ __align__(16) __half g_wtT[9 * COUT * CIN];      // [tap][co][ci]
__device__ __align__(16) __half g_xsT[B * 66 * 66 * CIN];   // zero halo [b][y+1][x+1][ci]
__device__ __align__(16) __half g_midp[4][B * COUT * 65 * 68];  // parity planes

__device__ __forceinline__ uint32_t smem_u32(const void* p) {
    uint32_t a;
    asm("{ .reg .u64 t; cvta.to.shared.u64 t, %1; cvt.u32.u64 %0, t; }"
        : "=r"(a) : "l"(p));
    return a;
}
__device__ __forceinline__ uint32_t sw128(uint32_t o) { return o ^ ((o >> 3) & 0x70); }

#define CP_ASYNC16(dst, src) \
    asm volatile("cp.async.cg.shared.global [%0], [%1], 16;" \
                 :: "r"(dst), "l"(src) : "memory")
#define CP_COMMIT() asm volatile("cp.async.commit_group;" ::: "memory")
#define CP_WAIT1()  asm volatile("cp.async.wait_group 1;" ::: "memory")
#define CP_WAIT0()  asm volatile("cp.async.wait_group 0;" ::: "memory")

// ---------------------------------------------------------------------------
// Kernel 1: s[b][ci] = style[b]·modW[ci]/sqrt(512) + bias[ci]
// ---------------------------------------------------------------------------
__global__ void k_style(const float* __restrict__ style,
                        const float* __restrict__ modw,
                        const float* __restrict__ modb) {
    int b = blockIdx.x;
    int ci = threadIdx.x;
    __shared__ __align__(16) float ss[CIN];
    ss[ci] = style[b * CIN + ci];
    __syncthreads();
    const float4* row = reinterpret_cast<const float4*>(modw + ci * CIN);
    const float4* s4p = reinterpret_cast<const float4*>(ss);
    float acc = 0.f;
#pragma unroll 4
    for (int k = 0; k < CIN / 4; k++) {
        float4 m = row[k];
        float4 s4 = s4p[k];
        acc += m.x * s4.x + m.y * s4.y + m.z * s4.z + m.w * s4.w;
    }
    g_s[b * CIN + ci] = acc * 0.044194173824159216f + modb[ci];
}

// ---------------------------------------------------------------------------
// Kernel 2: g_wtT[tap][co][ci] = half(scale * weight[co][ci][tap])
// ---------------------------------------------------------------------------
__global__ void k_wtT(const float* __restrict__ weight) {
    int co = blockIdx.x;
    __shared__ float sw[CIN * 9];
    for (int e = threadIdx.x; e < CIN * 9; e += 256) sw[e] = weight[co * CIN * 9 + e];
    __syncthreads();
    for (int e = threadIdx.x; e < CIN * 9; e += 256) {
        int tap = e >> 9, ci = e & 511;
        g_wtT[(tap * COUT + co) * CIN + ci] =
            __float2half_rn(0.014731391274719739f * sw[ci * 9 + tap]);
    }
}

// ---------------------------------------------------------------------------
// Kernel 3a: zero the halo of g_xsT (y1 in {0,65} or x1 in {0,65})
// ---------------------------------------------------------------------------
__global__ void k_halo() {
    int b = blockIdx.y;
    int idx = blockIdx.x * 256 + threadIdx.x;   // half2 units
    int px = idx >> 8, cp = idx & 255;          // 256 half2 per pixel
    if (px >= 260) return;
    int y1, x1;
    if (px < 66)       { y1 = 0;  x1 = px; }
    else if (px < 132) { y1 = 65; x1 = px - 66; }
    else if (px < 196) { y1 = px - 132 + 1; x1 = 0; }
    else               { y1 = px - 196 + 1; x1 = 65; }
    reinterpret_cast<__half2*>(
        g_xsT + ((size_t)(b * 66 + y1) * 66 + x1) * CIN)[cp] =
        __floats2half2_rn(0.f, 0.f);
}

// ---------------------------------------------------------------------------
// Kernel 3b: g_xsT[b][y+1][x+1][ci] = half(x[b][ci][y][x] * s[b][ci])
// ci split over blockIdx.z (4 slices of 128)
// ---------------------------------------------------------------------------
__global__ void k_xsT(const float* __restrict__ x) {
    int y = blockIdx.x, b = blockIdx.y;
    int cib = blockIdx.z * 128;
    __shared__ float t[32][65];
    const float* xb = x + (size_t)b * CIN * H * W + y * W;
    __half* ob = g_xsT + ((size_t)(b * 66 + y + 1) * 66 + 1) * CIN;
    for (int cc = 0; cc < 4; cc++) {
        int ci0 = cib + cc * 32;
        __syncthreads();
#pragma unroll
        for (int k = 0; k < 8; k++) {
            int e = threadIdx.x + k * 256;
            int ci = e >> 6, xc = e & 63;
            float s = g_s[b * CIN + ci0 + ci];
            t[ci][xc] = xb[(ci0 + ci) * H * W + xc] * s;
        }
        __syncthreads();
#pragma unroll
        for (int k = 0; k < 4; k++) {
            int e = threadIdx.x + k * 256;
            int xc = e >> 4, cp = e & 15;
            __half2 h = __floats2half2_rn(t[cp * 2][xc], t[cp * 2 + 1][xc]);
            *(reinterpret_cast<__half2*>(ob + (size_t)xc * CIN + ci0) + cp) = h;
        }
    }
}

// ---------------------------------------------------------------------------
// Kernel 4: demod[b][co] (exact fp32, 256 blocks — parallel)
// ---------------------------------------------------------------------------
__global__ void k_demod(const float* __restrict__ weight) {
    int co = blockIdx.x;
    int tid = threadIdx.x;
    __shared__ float sred[8][8];
    float part[B];
#pragma unroll
    for (int b = 0; b < B; b++) part[b] = 0.f;
    for (int cc = 0; cc < 2; cc++) {
        int ci = tid + cc * 256;
        float q = 0.f;
        const float* wr = weight + (co * CIN + ci) * 9;
#pragma unroll
        for (int k = 0; k < 9; k++) { float w = wr[k]; q += w * w; }
#pragma unroll
        for (int b = 0; b < B; b++) {
            float s = g_s[b * CIN + ci];
            part[b] += q * s * s;
        }
    }
#pragma unroll
    for (int b = 0; b < B; b++) {
#pragma unroll
        for (int o = 16; o; o >>= 1)
            part[b] += __shfl_xor_sync(0xffffffffu, part[b], o);
    }
    if ((tid & 31) == 0) {
#pragma unroll
        for (int b = 0; b < B; b++) sred[b][tid >> 5] = part[b];
    }
    __syncthreads();
    if (tid < B) {
        float s = 0.f;
#pragma unroll
        for (int w = 0; w < 8; w++) s += sred[tid][w];
        const float sc2 = 0.014731391274719739f * 0.014731391274719739f;
        g_demod[tid * COUT + co] = rsqrtf(sc2 * s + 1e-8f);
    }
}

// ---------------------------------------------------------------------------
// Kernel 5: conv (round-13 proven config): all four parities, one launch.
// CTA: 128 co x 128 px, 256 threads, 2 CTA/SM, 3-stage cp.async pipeline.
// ---------------------------------------------------------------------------
#define SM_US   0
#define SM_VS   512
#define SM_UE   1024
#define SM_BUF  2048
#define SM_DYN  100352

__global__ void __launch_bounds__(256, 2) k_conv() {
    extern __shared__ __align__(1024) char smem[];
    const uint32_t sb = smem_u32(smem);
    int* us = (int*)(smem + SM_US);
    int* vs = (int*)(smem + SM_VS);
    int* ue = (int*)(smem + SM_UE);

    const int tid = threadIdx.x;
    const int lane = tid & 31, warp = tid >> 5;
    const int g = lane >> 2, tg = lane & 3;
    const int wm = warp >> 1, wn = warp & 1;
    const int cobase = blockIdx.y * 128;
    const int b = blockIdx.z;

    int bx = blockIdx.x;
    int py, px, xt;
    if (bx < 34)       { py = 0; px = 0; xt = bx; }
    else if (bx < 67)  { py = 0; px = 1; xt = bx - 34; }
    else if (bx < 100) { py = 1; px = 0; xt = bx - 67; }
    else               { py = 1; px = 1; xt = bx - 100; }
    const int U = 65 - py, V = 65 - px;
    const int NPIX = U * V;
    const int nky = 2 - py, nkx = 2 - px;
    const int NC = nky * nkx * 8;
    const int n0 = xt * 128;

    {
        int p = n0 + tid;
        int u = p / V, v = p - u * V;
        bool ok = (p < NPIX);
        if (tid < 128) {
            us[tid] = ok ? u : 0;
            vs[tid] = ok ? v : 0;
            ue[tid] = ok ? u : -1;
        }
    }
    __syncthreads();

    const __half* xb = g_xsT + (size_t)b * 66 * 66 * CIN;

    auto issue = [&](int gidx) {
        const int t = gidx >> 3;
        const int ci0 = (gidx & 7) * 64;
        const int iy = (nkx == 2) ? (t >> 1) : t;
        const int ix = t - iy * nkx;
        const int ky = (py == 0) ? iy * 2 : 1;
        const int kx = (px == 0) ? ix * 2 : 1;
        const int dy = (py == 0) ? iy : 0;
        const int dx = (px == 0) ? ix : 0;
        const int bufi = gidx - (gidx / 3) * 3;
        const uint32_t Ab = sb + SM_BUF + bufi * 32768;
        const uint32_t Bb = Ab + 16384;
        const __half* wt = g_wtT + (ky * 3 + kx) * COUT * CIN + ci0;
#pragma unroll
        for (int k = 0; k < 4; k++) {
            int f = tid + k * 256;
            int co = f >> 3, q = f & 7;
            const __half* src = wt + (size_t)(cobase + co) * CIN + q * 8;
            CP_ASYNC16(Ab + sw128(co * 128 + q * 16), src);
        }
#pragma unroll
        for (int k = 0; k < 4; k++) {
            int f = tid + k * 256;
            int j = f >> 3, q = f & 7;
            int y1 = us[j] + 1 - dy, x1 = vs[j] + 1 - dx;
            const __half* src = xb + ((size_t)(y1 * 66 + x1)) * CIN + ci0 + q * 8;
            CP_ASYNC16(Bb + sw128(j * 128 + q * 16), src);
        }
        CP_COMMIT();
    };

    float acc[2][8][4];
#pragma unroll
    for (int mi = 0; mi < 2; mi++)
#pragma unroll
        for (int nt = 0; nt < 8; nt++)
#pragma unroll
            for (int r = 0; r < 4; r++) acc[mi][nt][r] = 0.f;

    issue(0);
    issue(1);

    const int arow = wm * 32 + (lane & 15);
    const int acolb = (lane >> 4) * 16;
    const int brow = wn * 64 + ((lane >> 4) << 3) + (lane & 7);
    const int bcolb = ((lane >> 3) & 1) * 16;

#pragma unroll 1
    for (int c = 0; c < NC; c++) {
        if (c == NC - 1) { CP_WAIT0(); } else { CP_WAIT1(); }
        __syncthreads();
        if (c + 2 < NC) issue(c + 2);
        const int bufi = c - (c / 3) * 3;
        const uint32_t Ab = sb + SM_BUF + bufi * 32768;
        const uint32_t Bb = Ab + 16384;
#pragma unroll
        for (int ks = 0; ks < 4; ks++) {
            uint32_t a[2][4], bb[8][2];
#pragma unroll
            for (int mi = 0; mi < 2; mi++) {
                uint32_t addr = Ab + sw128((arow + mi * 16) * 128 + acolb + ks * 32);
                asm volatile(
                    "ldmatrix.sync.aligned.m8n8.x4.shared.b16 {%0,%1,%2,%3}, [%4];"
                    : "=r"(a[mi][0]), "=r"(a[mi][1]), "=r"(a[mi][2]), "=r"(a[mi][3])
                    : "r"(addr) : "memory");
            }
#pragma unroll
            for (int ntp = 0; ntp < 4; ntp++) {
                uint32_t addr = Bb + sw128((brow + ntp * 16) * 128 + bcolb + ks * 32);
                uint32_t r0, r1, r2, r3;
                asm volatile(
                    "ldmatrix.sync.aligned.m8n8.x4.shared.b16 {%0,%1,%2,%3}, [%4];"
                    : "=r"(r0), "=r"(r1), "=r"(r2), "=r"(r3)
                    : "r"(addr) : "memory");
                bb[ntp * 2][0] = r0;     bb[ntp * 2][1] = r1;
                bb[ntp * 2 + 1][0] = r2; bb[ntp * 2 + 1][1] = r3;
            }
#pragma unroll
            for (int mi = 0; mi < 2; mi++)
#pragma unroll
                for (int nt = 0; nt < 8; nt++) {
                    asm volatile(
                        "mma.sync.aligned.m16n8k16.row.col.f32.f16.f16.f32 "
                        "{%0,%1,%2,%3}, {%4,%5,%6,%7}, {%8,%9}, {%0,%1,%2,%3};"
                        : "+f"(acc[mi][nt][0]), "+f"(acc[mi][nt][1]),
                          "+f"(acc[mi][nt][2]), "+f"(acc[mi][nt][3])
                        : "r"(a[mi][0]), "r"(a[mi][1]), "r"(a[mi][2]),
                          "r"(a[mi][3]), "r"(bb[nt][0]), "r"(bb[nt][1]));
                }
        }
    }

    __half* plane = g_midp[py * 2 + px];
#pragma unroll
    for (int mi = 0; mi < 2; mi++) {
        int r0 = cobase + wm * 32 + mi * 16 + g;
        float d0 = g_demod[b * COUT + r0];
        float d1 = g_demod[b * COUT + r0 + 8];
        __half* p0 = plane + (size_t)(b * COUT + r0) * 65 * 68;
        __half* p1 = plane + (size_t)(b * COUT + r0 + 8) * 65 * 68;
#pragma unroll
        for (int nt = 0; nt < 8; nt++) {
            int j = wn * 64 + nt * 8 + tg * 2;
            int u0 = ue[j], u1 = ue[j + 1];
            int v0 = vs[j], v1 = vs[j + 1];
            if (u0 >= 0 && u1 == u0 && v1 == v0 + 1 && (v0 & 1) == 0) {
                __half2 h0 = __floats2half2_rn(acc[mi][nt][0] * d0,
                                               acc[mi][nt][1] * d0);
                __half2 h1 = __floats2half2_rn(acc[mi][nt][2] * d1,
                                               acc[mi][nt][3] * d1);
                *reinterpret_cast<__half2*>(p0 + u0 * 68 + v0) = h0;
                *reinterpret_cast<__half2*>(p1 + u0 * 68 + v0) = h1;
            } else {
                if (u0 >= 0) {
                    p0[u0 * 68 + v0] = __float2half_rn(acc[mi][nt][0] * d0);
                    p1[u0 * 68 + v0] = __float2half_rn(acc[mi][nt][2] * d1);
                }
                if (u1 >= 0) {
                    p0[u1 * 68 + v1] = __float2half_rn(acc[mi][nt][1] * d0);
                    p1[u1 * 68 + v1] = __float2half_rn(acc[mi][nt][3] * d1);
                }
            }
        }
    }
}

// ---------------------------------------------------------------------------
// Kernel 6: plane-resident blur, X-pair per thread (2.5 LDS per output).
// Thread: v = tid&63 -> outputs X=2v, 2v+1; strip = tid>>6 -> 16 u rows.
// Per u: 2 HS2 calls (5 LDS each) produce hs for BOTH X parities of 2 rows,
// rolling over u; float2 coalesced stores.
// ---------------------------------------------------------------------------
#define PLN 4420  // 65*68 halves per plane

__global__ void __launch_bounds__(256) k_blur(float* __restrict__ out) {
    int bc = blockIdx.x;
    __shared__ __align__(16) __half sm[8 + 4 * PLN];
    const int tid = threadIdx.x;

    for (int e = tid; e < 4 * 65 * 17; e += 256) {
        int p = e / (65 * 17);
        int rem = e - p * 65 * 17;
        int r = rem / 17, c4 = rem - r * 17;
        uint2 val = *reinterpret_cast<const uint2*>(
            g_midp[p] + (size_t)bc * PLN + r * 68 + c4 * 4);
        *reinterpret_cast<uint2*>(sm + 8 + p * PLN + r * 68 + c4 * 4) = val;
    }
    if (tid < 8) sm[tid] = __float2half(0.f);
    __syncthreads();
    // zero invalid cells: cols >= V (all rows), and row 64 of py=1 planes
#pragma unroll
    for (int p = 0; p < 4; p++) {
        int Vp = 65 - (p & 1);
        int nc = 68 - Vp;
        for (int e = tid; e < 65 * nc; e += 256) {
            int rr = e / nc, cc = e - rr * nc;
            sm[8 + p * PLN + rr * 68 + Vp + cc] = __float2half(0.f);
        }
        if (p >> 1) {
            for (int e = tid; e < 68; e += 256)
                sm[8 + p * PLN + 64 * 68 + e] = __float2half(0.f);
        }
    }
    __syncthreads();

    const int v = tid & 63, strip = tid >> 6;
    const __half* sp = sm + 8;
    const __half* pE0 = sp;             // py0 px0
    const __half* pO0 = sp + PLN;       // py0 px1
    const __half* pE1 = sp + 2 * PLN;   // py1 px0
    const __half* pO1 = sp + 3 * PLN;   // py1 px1

    // hs for X=2v (h0) and X=2v+1 (h1) of mid row with given E/O planes, row r
    auto HS2 = [&](const __half* E, const __half* O, int r,
                   float& h0, float& h1) {
        const __half* Er = E + r * 68;
        const __half* Or = O + r * 68;
        float e0 = __half2float(Er[v]);
        float e1 = __half2float(Er[v + 1]);
        float om = __half2float(Or[v - 1]);   // v=0,r=0,p=0 hits guard sm[7]=0
        float o0 = __half2float(Or[v]);
        float o1 = __half2float(Or[v + 1]);
        h0 = om + 3.f * e0 + 3.f * o0 + e1;
        h1 = e0 + 3.f * o0 + 3.f * e1 + o1;
    };

    const int u0 = strip * 16;
    float hoP0, hoP1;                      // hsO(u-1)
    if (u0 == 0) { hoP0 = 0.f; hoP1 = 0.f; }
    else HS2(pE1, pO1, u0 - 1, hoP0, hoP1);
    float heC0, heC1, hoC0, hoC1;          // hsE(u), hsO(u)
    HS2(pE0, pO0, u0, heC0, heC1);
    HS2(pE1, pO1, u0, hoC0, hoC1);

    float* ob = out + (size_t)bc * 16384 + 2 * v;
#pragma unroll 4
    for (int u = u0; u < u0 + 16; u++) {
        float heN0, heN1, hoN0, hoN1;
        HS2(pE0, pO0, u + 1, heN0, heN1);  // row 64 valid; row 64 of py1 zeroed
        HS2(pE1, pO1, u + 1, hoN0, hoN1);
        float2 r0, r1;
        r0.x = (hoP0 + 3.f * heC0 + 3.f * hoC0 + heN0) * (1.f / 16.f);
        r0.y = (hoP1 + 3.f * heC1 + 3.f * hoC1 + heN1) * (1.f / 16.f);
        r1.x = (heC0 + 3.f * hoC0 + 3.f * heN0 + hoN0) * (1.f / 16.f);
        r1.y = (heC1 + 3.f * hoC1 + 3.f * heN1 + hoN1) * (1.f / 16.f);
        *reinterpret_cast<float2*>(ob + (2 * u) * 128) = r0;
        *reinterpret_cast<float2*>(ob + (2 * u + 1) * 128) = r1;
        hoP0 = hoC0; hoP1 = hoC1;
        heC0 = heN0; heC1 = heN1;
        hoC0 = hoN0; hoC1 = hoN1;
    }
}

// ---------------------------------------------------------------------------
extern "C" void kernel_launch(void* const* d_in, const int* in_sizes, int n_in,
                              void* d_out, int out_size) {
    const float* input  = (const float*)d_in[0];
    const float* style  = (const float*)d_in[1];
    const float* weight = (const float*)d_in[2];
    const float* modw   = (const float*)d_in[3];
    const float* modb   = (const float*)d_in[4];
    float* out = (float*)d_out;

    cudaFuncSetAttribute(k_conv, cudaFuncAttributeMaxDynamicSharedMemorySize, SM_DYN);

    k_style<<<B, CIN>>>(style, modw, modb);
    k_wtT<<<COUT, 256>>>(weight);
    k_halo<<<dim3(260, B), 256>>>();
    k_xsT<<<dim3(H, B, 4), 256>>>(input);
    k_demod<<<COUT, 256>>>(weight);

    k_conv<<<dim3(132, 2, B), 256, SM_DYN>>>();

    k_blur<<<B * COUT, 256>>>(out);
}

// round 16
// speedup vs baseline: 1.1277x; 1.0650x over previous
#include <cuda_runtime.h>
#include <cuda_fp16.h>
#include <math.h>
#include <stdint.h>

#define B    8
#define CIN  512
#define COUT 256
#define H    64
#define W    64

// ---------------- static device scratch (16B-aligned for cp.async) ----------
__device__ __align__(16) float  g_s[B * CIN];
__device__ __align__(16) float  g_demod[B * COUT];
__device__ __align__(16) __half g_wtT[9 * COUT * CIN];      // [tap][co][ci]
__device__ __align__(16) __half g_xsT[B * 66 * 66 * CIN];   // zero halo [b][y+1][x+1][ci]
__device__ __align__(16) __half g_midp[4][B * COUT * 65 * 68];  // parity planes

__device__ __forceinline__ uint32_t smem_u32(const void* p) {
    uint32_t a;
    asm("{ .reg .u64 t; cvta.to.shared.u64 t, %1; cvt.u32.u64 %0, t; }"
        : "=r"(a) : "l"(p));
    return a;
}
__device__ __forceinline__ uint32_t sw128(uint32_t o) { return o ^ ((o >> 3) & 0x70); }

#define CP_ASYNC16(dst, src) \
    asm volatile("cp.async.cg.shared.global [%0], [%1], 16;" \
                 :: "r"(dst), "l"(src) : "memory")
#define CP_COMMIT() asm volatile("cp.async.commit_group;" ::: "memory")
#define CP_WAIT1()  asm volatile("cp.async.wait_group 1;" ::: "memory")
#define CP_WAIT0()  asm volatile("cp.async.wait_group 0;" ::: "memory")

// ---------------------------------------------------------------------------
// Kernel 1: s[b][ci] = style[b]·modW[ci]/sqrt(512) + bias[ci]
// ---------------------------------------------------------------------------
__global__ void k_style(const float* __restrict__ style,
                        const float* __restrict__ modw,
                        const float* __restrict__ modb) {
    int b = blockIdx.x;
    int ci = threadIdx.x;
    __shared__ __align__(16) float ss[CIN];
    ss[ci] = style[b * CIN + ci];
    __syncthreads();
    const float4* row = reinterpret_cast<const float4*>(modw + ci * CIN);
    const float4* s4p = reinterpret_cast<const float4*>(ss);
    float acc = 0.f;
#pragma unroll 4
    for (int k = 0; k < CIN / 4; k++) {
        float4 m = row[k];
        float4 s4 = s4p[k];
        acc += m.x * s4.x + m.y * s4.y + m.z * s4.z + m.w * s4.w;
    }
    g_s[b * CIN + ci] = acc * 0.044194173824159216f + modb[ci];
}

// ---------------------------------------------------------------------------
// Kernel 2: g_wtT[tap][co][ci] = half(scale * weight[co][ci][tap])
// ---------------------------------------------------------------------------
__global__ void k_wtT(const float* __restrict__ weight) {
    int co = blockIdx.x;
    __shared__ float sw[CIN * 9];
    for (int e = threadIdx.x; e < CIN * 9; e += 256) sw[e] = weight[co * CIN * 9 + e];
    __syncthreads();
    for (int e = threadIdx.x; e < CIN * 9; e += 256) {
        int tap = e >> 9, ci = e & 511;
        g_wtT[(tap * COUT + co) * CIN + ci] =
            __float2half_rn(0.014731391274719739f * sw[ci * 9 + tap]);
    }
}

// ---------------------------------------------------------------------------
// Kernel 3a: zero the halo of g_xsT (y1 in {0,65} or x1 in {0,65})
// ---------------------------------------------------------------------------
__global__ void k_halo() {
    int b = blockIdx.y;
    int idx = blockIdx.x * 256 + threadIdx.x;   // half2 units
    int px = idx >> 8, cp = idx & 255;          // 256 half2 per pixel
    if (px >= 260) return;
    int y1, x1;
    if (px < 66)       { y1 = 0;  x1 = px; }
    else if (px < 132) { y1 = 65; x1 = px - 66; }
    else if (px < 196) { y1 = px - 132 + 1; x1 = 0; }
    else               { y1 = px - 196 + 1; x1 = 65; }
    reinterpret_cast<__half2*>(
        g_xsT + ((size_t)(b * 66 + y1) * 66 + x1) * CIN)[cp] =
        __floats2half2_rn(0.f, 0.f);
}

// ---------------------------------------------------------------------------
// Kernel 3b: g_xsT[b][y+1][x+1][ci] = half(x[b][ci][y][x] * s[b][ci])
// ci split over blockIdx.z (4 slices of 128)
// ---------------------------------------------------------------------------
__global__ void k_xsT(const float* __restrict__ x) {
    int y = blockIdx.x, b = blockIdx.y;
    int cib = blockIdx.z * 128;
    __shared__ float t[32][65];
    const float* xb = x + (size_t)b * CIN * H * W + y * W;
    __half* ob = g_xsT + ((size_t)(b * 66 + y + 1) * 66 + 1) * CIN;
    for (int cc = 0; cc < 4; cc++) {
        int ci0 = cib + cc * 32;
        __syncthreads();
#pragma unroll
        for (int k = 0; k < 8; k++) {
            int e = threadIdx.x + k * 256;
            int ci = e >> 6, xc = e & 63;
            float s = g_s[b * CIN + ci0 + ci];
            t[ci][xc] = xb[(ci0 + ci) * H * W + xc] * s;
        }
        __syncthreads();
#pragma unroll
        for (int k = 0; k < 4; k++) {
            int e = threadIdx.x + k * 256;
            int xc = e >> 4, cp = e & 15;
            __half2 h = __floats2half2_rn(t[cp * 2][xc], t[cp * 2 + 1][xc]);
            *(reinterpret_cast<__half2*>(ob + (size_t)xc * CIN + ci0) + cp) = h;
        }
    }
}

// ---------------------------------------------------------------------------
// Kernel 4: demod[b][co] (exact fp32, 256 blocks — parallel)
// ---------------------------------------------------------------------------
__global__ void k_demod(const float* __restrict__ weight) {
    int co = blockIdx.x;
    int tid = threadIdx.x;
    __shared__ float sred[8][8];
    float part[B];
#pragma unroll
    for (int b = 0; b < B; b++) part[b] = 0.f;
    for (int cc = 0; cc < 2; cc++) {
        int ci = tid + cc * 256;
        float q = 0.f;
        const float* wr = weight + (co * CIN + ci) * 9;
#pragma unroll
        for (int k = 0; k < 9; k++) { float w = wr[k]; q += w * w; }
#pragma unroll
        for (int b = 0; b < B; b++) {
            float s = g_s[b * CIN + ci];
            part[b] += q * s * s;
        }
    }
#pragma unroll
    for (int b = 0; b < B; b++) {
#pragma unroll
        for (int o = 16; o; o >>= 1)
            part[b] += __shfl_xor_sync(0xffffffffu, part[b], o);
    }
    if ((tid & 31) == 0) {
#pragma unroll
        for (int b = 0; b < B; b++) sred[b][tid >> 5] = part[b];
    }
    __syncthreads();
    if (tid < B) {
        float s = 0.f;
#pragma unroll
        for (int w = 0; w < 8; w++) s += sred[tid][w];
        const float sc2 = 0.014731391274719739f * 0.014731391274719739f;
        g_demod[tid * COUT + co] = rsqrtf(sc2 * s + 1e-8f);
    }
}

// ---------------------------------------------------------------------------
// Kernel 5: conv — FAT WARP config. All four parities, one launch.
// CTA: 128 co x 128 px, 128 threads (4 warps: 2wm x 2wn, 64co x 64px each).
// Per warp-kstep: 8 LDSM -> 32 HMMA (was 6 -> 16). 2 CTA/SM.
// 3-stage cp.async pipeline, one __syncthreads per 64-ci chunk.
// ---------------------------------------------------------------------------
#define SM_US   0
#define SM_VS   512
#define SM_UE   1024
#define SM_BUF  2048
#define SM_DYN  100352

__global__ void __launch_bounds__(128, 2) k_conv() {
    extern __shared__ __align__(1024) char smem[];
    const uint32_t sb = smem_u32(smem);
    int* us = (int*)(smem + SM_US);
    int* vs = (int*)(smem + SM_VS);
    int* ue = (int*)(smem + SM_UE);

    const int tid = threadIdx.x;
    const int lane = tid & 31, warp = tid >> 5;
    const int g = lane >> 2, tg = lane & 3;
    const int wm = warp >> 1, wn = warp & 1;   // 2x2 warps, 64co x 64px each
    const int cobase = blockIdx.y * 128;
    const int b = blockIdx.z;

    int bx = blockIdx.x;
    int py, px, xt;
    if (bx < 34)       { py = 0; px = 0; xt = bx; }
    else if (bx < 67)  { py = 0; px = 1; xt = bx - 34; }
    else if (bx < 100) { py = 1; px = 0; xt = bx - 67; }
    else               { py = 1; px = 1; xt = bx - 100; }
    const int U = 65 - py, V = 65 - px;
    const int NPIX = U * V;
    const int nky = 2 - py, nkx = 2 - px;
    const int NC = nky * nkx * 8;
    const int n0 = xt * 128;

    {
        int p = n0 + tid;
        int u = p / V, v = p - u * V;
        bool ok = (p < NPIX);
        us[tid] = ok ? u : 0;
        vs[tid] = ok ? v : 0;
        ue[tid] = ok ? u : -1;
    }
    __syncthreads();

    const __half* xb = g_xsT + (size_t)b * 66 * 66 * CIN;

    auto issue = [&](int gidx) {
        const int t = gidx >> 3;
        const int ci0 = (gidx & 7) * 64;
        const int iy = (nkx == 2) ? (t >> 1) : t;
        const int ix = t - iy * nkx;
        const int ky = (py == 0) ? iy * 2 : 1;
        const int kx = (px == 0) ? ix * 2 : 1;
        const int dy = (py == 0) ? iy : 0;
        const int dx = (px == 0) ? ix : 0;
        const int bufi = gidx - (gidx / 3) * 3;
        const uint32_t Ab = sb + SM_BUF + bufi * 32768;
        const uint32_t Bb = Ab + 16384;
        const __half* wt = g_wtT + (ky * 3 + kx) * COUT * CIN + ci0;
#pragma unroll
        for (int k = 0; k < 8; k++) {
            int f = tid + k * 128;
            int co = f >> 3, q = f & 7;
            const __half* src = wt + (size_t)(cobase + co) * CIN + q * 8;
            CP_ASYNC16(Ab + sw128(co * 128 + q * 16), src);
        }
#pragma unroll
        for (int k = 0; k < 8; k++) {
            int f = tid + k * 128;
            int j = f >> 3, q = f & 7;
            int y1 = us[j] + 1 - dy, x1 = vs[j] + 1 - dx;
            const __half* src = xb + ((size_t)(y1 * 66 + x1)) * CIN + ci0 + q * 8;
            CP_ASYNC16(Bb + sw128(j * 128 + q * 16), src);
        }
        CP_COMMIT();
    };

    float acc[4][8][4];
#pragma unroll
    for (int mi = 0; mi < 4; mi++)
#pragma unroll
        for (int nt = 0; nt < 8; nt++)
#pragma unroll
            for (int r = 0; r < 4; r++) acc[mi][nt][r] = 0.f;

    issue(0);
    issue(1);

    const int arow = wm * 64 + (lane & 15);
    const int acolb = (lane >> 4) * 16;
    const int brow = wn * 64 + ((lane >> 4) << 3) + (lane & 7);
    const int bcolb = ((lane >> 3) & 1) * 16;

#pragma unroll 1
    for (int c = 0; c < NC; c++) {
        if (c == NC - 1) { CP_WAIT0(); } else { CP_WAIT1(); }
        __syncthreads();
        if (c + 2 < NC) issue(c + 2);
        const int bufi = c - (c / 3) * 3;
        const uint32_t Ab = sb + SM_BUF + bufi * 32768;
        const uint32_t Bb = Ab + 16384;
#pragma unroll
        for (int ks = 0; ks < 4; ks++) {
            uint32_t a[4][4], bb[8][2];
#pragma unroll
            for (int mi = 0; mi < 4; mi++) {
                uint32_t addr = Ab + sw128((arow + mi * 16) * 128 + acolb + ks * 32);
                asm volatile(
                    "ldmatrix.sync.aligned.m8n8.x4.shared.b16 {%0,%1,%2,%3}, [%4];"
                    : "=r"(a[mi][0]), "=r"(a[mi][1]), "=r"(a[mi][2]), "=r"(a[mi][3])
                    : "r"(addr) : "memory");
            }
#pragma unroll
            for (int ntp = 0; ntp < 4; ntp++) {
                uint32_t addr = Bb + sw128((brow + ntp * 16) * 128 + bcolb + ks * 32);
                uint32_t r0, r1, r2, r3;
                asm volatile(
                    "ldmatrix.sync.aligned.m8n8.x4.shared.b16 {%0,%1,%2,%3}, [%4];"
                    : "=r"(r0), "=r"(r1), "=r"(r2), "=r"(r3)
                    : "r"(addr) : "memory");
                bb[ntp * 2][0] = r0;     bb[ntp * 2][1] = r1;
                bb[ntp * 2 + 1][0] = r2; bb[ntp * 2 + 1][1] = r3;
            }
#pragma unroll
            for (int mi = 0; mi < 4; mi++)
#pragma unroll
                for (int nt = 0; nt < 8; nt++) {
                    asm volatile(
                        "mma.sync.aligned.m16n8k16.row.col.f32.f16.f16.f32 "
                        "{%0,%1,%2,%3}, {%4,%5,%6,%7}, {%8,%9}, {%0,%1,%2,%3};"
                        : "+f"(acc[mi][nt][0]), "+f"(acc[mi][nt][1]),
                          "+f"(acc[mi][nt][2]), "+f"(acc[mi][nt][3])
                        : "r"(a[mi][0]), "r"(a[mi][1]), "r"(a[mi][2]),
                          "r"(a[mi][3]), "r"(bb[nt][0]), "r"(bb[nt][1]));
                }
        }
    }

    __half* plane = g_midp[py * 2 + px];
#pragma unroll
    for (int mi = 0; mi < 4; mi++) {
        int r0 = cobase + wm * 64 + mi * 16 + g;
        float d0 = g_demod[b * COUT + r0];
        float d1 = g_demod[b * COUT + r0 + 8];
        __half* p0 = plane + (size_t)(b * COUT + r0) * 65 * 68;
        __half* p1 = plane + (size_t)(b * COUT + r0 + 8) * 65 * 68;
#pragma unroll
        for (int nt = 0; nt < 8; nt++) {
            int j = wn * 64 + nt * 8 + tg * 2;
            int u0 = ue[j], u1 = ue[j + 1];
            int v0 = vs[j], v1 = vs[j + 1];
            if (u0 >= 0 && u1 == u0 && v1 == v0 + 1 && (v0 & 1) == 0) {
                __half2 h0 = __floats2half2_rn(acc[mi][nt][0] * d0,
                                               acc[mi][nt][1] * d0);
                __half2 h1 = __floats2half2_rn(acc[mi][nt][2] * d1,
                                               acc[mi][nt][3] * d1);
                *reinterpret_cast<__half2*>(p0 + u0 * 68 + v0) = h0;
                *reinterpret_cast<__half2*>(p1 + u0 * 68 + v0) = h1;
            } else {
                if (u0 >= 0) {
                    p0[u0 * 68 + v0] = __float2half_rn(acc[mi][nt][0] * d0);
                    p1[u0 * 68 + v0] = __float2half_rn(acc[mi][nt][2] * d1);
                }
                if (u1 >= 0) {
                    p0[u1 * 68 + v1] = __float2half_rn(acc[mi][nt][1] * d0);
                    p1[u1 * 68 + v1] = __float2half_rn(acc[mi][nt][3] * d1);
                }
            }
        }
    }
}

// ---------------------------------------------------------------------------
// Kernel 6: plane-resident blur, X-pair per thread (2.5 LDS per output).
// ---------------------------------------------------------------------------
#define PLN 4420  // 65*68 halves per plane

__global__ void __launch_bounds__(256) k_blur(float* __restrict__ out) {
    int bc = blockIdx.x;
    __shared__ __align__(16) __half sm[8 + 4 * PLN];
    const int tid = threadIdx.x;

    for (int e = tid; e < 4 * 65 * 17; e += 256) {
        int p = e / (65 * 17);
        int rem = e - p * 65 * 17;
        int r = rem / 17, c4 = rem - r * 17;
        uint2 val = *reinterpret_cast<const uint2*>(
            g_midp[p] + (size_t)bc * PLN + r * 68 + c4 * 4);
        *reinterpret_cast<uint2*>(sm + 8 + p * PLN + r * 68 + c4 * 4) = val;
    }
    if (tid < 8) sm[tid] = __float2half(0.f);
    __syncthreads();
#pragma unroll
    for (int p = 0; p < 4; p++) {
        int Vp = 65 - (p & 1);
        int nc = 68 - Vp;
        for (int e = tid; e < 65 * nc; e += 256) {
            int rr = e / nc, cc = e - rr * nc;
            sm[8 + p * PLN + rr * 68 + Vp + cc] = __float2half(0.f);
        }
        if (p >> 1) {
            for (int e = tid; e < 68; e += 256)
                sm[8 + p * PLN + 64 * 68 + e] = __float2half(0.f);
        }
    }
    __syncthreads();

    const int v = tid & 63, strip = tid >> 6;
    const __half* sp = sm + 8;
    const __half* pE0 = sp;
    const __half* pO0 = sp + PLN;
    const __half* pE1 = sp + 2 * PLN;
    const __half* pO1 = sp + 3 * PLN;

    auto HS2 = [&](const __half* E, const __half* O, int r,
                   float& h0, float& h1) {
        const __half* Er = E + r * 68;
        const __half* Or = O + r * 68;
        float e0 = __half2float(Er[v]);
        float e1 = __half2float(Er[v + 1]);
        float om = __half2float(Or[v - 1]);
        float o0 = __half2float(Or[v]);
        float o1 = __half2float(Or[v + 1]);
        h0 = om + 3.f * e0 + 3.f * o0 + e1;
        h1 = e0 + 3.f * o0 + 3.f * e1 + o1;
    };

    const int u0 = strip * 16;
    float hoP0, hoP1;
    if (u0 == 0) { hoP0 = 0.f; hoP1 = 0.f; }
    else HS2(pE1, pO1, u0 - 1, hoP0, hoP1);
    float heC0, heC1, hoC0, hoC1;
    HS2(pE0, pO0, u0, heC0, heC1);
    HS2(pE1, pO1, u0, hoC0, hoC1);

    float* ob = out + (size_t)bc * 16384 + 2 * v;
#pragma unroll 4
    for (int u = u0; u < u0 + 16; u++) {
        float heN0, heN1, hoN0, hoN1;
        HS2(pE0, pO0, u + 1, heN0, heN1);
        HS2(pE1, pO1, u + 1, hoN0, hoN1);
        float2 r0, r1;
        r0.x = (hoP0 + 3.f * heC0 + 3.f * hoC0 + heN0) * (1.f / 16.f);
        r0.y = (hoP1 + 3.f * heC1 + 3.f * hoC1 + heN1) * (1.f / 16.f);
        r1.x = (heC0 + 3.f * hoC0 + 3.f * heN0 + hoN0) * (1.f / 16.f);
        r1.y = (heC1 + 3.f * hoC1 + 3.f * heN1 + hoN1) * (1.f / 16.f);
        *reinterpret_cast<float2*>(ob + (2 * u) * 128) = r0;
        *reinterpret_cast<float2*>(ob + (2 * u + 1) * 128) = r1;
        hoP0 = hoC0; hoP1 = hoC1;
        heC0 = heN0; heC1 = heN1;
        hoC0 = hoN0; hoC1 = hoN1;
    }
}

// ---------------------------------------------------------------------------
extern "C" void kernel_launch(void* const* d_in, const int* in_sizes, int n_in,
                              void* d_out, int out_size) {
    const float* input  = (const float*)d_in[0];
    const float* style  = (const float*)d_in[1];
    const float* weight = (const float*)d_in[2];
    const float* modw   = (const float*)d_in[3];
    const float* modb   = (const float*)d_in[4];
    float* out = (float*)d_out;

    cudaFuncSetAttribute(k_conv, cudaFuncAttributeMaxDynamicSharedMemorySize, SM_DYN);

    k_style<<<B, CIN>>>(style, modw, modb);
    k_wtT<<<COUT, 256>>>(weight);
    k_halo<<<dim3(260, B), 256>>>();
    k_xsT<<<dim3(H, B, 4), 256>>>(input);
    k_demod<<<COUT, 256>>>(weight);

    k_conv<<<dim3(132, 2, B), 128, SM_DYN>>>();

    k_blur<<<B * COUT, 256>>>(out);
}

// round 17
// speedup vs baseline: 1.1525x; 1.0220x over previous
#include <cuda_runtime.h>
#include <cuda_fp16.h>
#include <math.h>
#include <stdint.h>

#define B    8
#define CIN  512
#define COUT 256
#define H    64
#define W    64

// ---------------- static device scratch (16B-aligned for cp.async) ----------
__device__ __align__(16) float  g_s[B * CIN];
__device__ __align__(16) float  g_demod[B * COUT];
__device__ __align__(16) __half g_wtT[9 * COUT * CIN];      // [tap][co][ci]
__device__ __align__(16) __half g_xsT[B * 66 * 66 * CIN];   // zero halo [b][y+1][x+1][ci]
__device__ __align__(16) __half g_midp[4][B * COUT * 65 * 68];  // parity planes

__device__ __forceinline__ uint32_t smem_u32(const void* p) {
    uint32_t a;
    asm("{ .reg .u64 t; cvta.to.shared.u64 t, %1; cvt.u32.u64 %0, t; }"
        : "=r"(a) : "l"(p));
    return a;
}
__device__ __forceinline__ uint32_t sw128(uint32_t o) { return o ^ ((o >> 3) & 0x70); }

#define CP_ASYNC16(dst, src) \
    asm volatile("cp.async.cg.shared.global [%0], [%1], 16;" \
                 :: "r"(dst), "l"(src) : "memory")
#define CP_COMMIT() asm volatile("cp.async.commit_group;" ::: "memory")
#define CP_WAIT1()  asm volatile("cp.async.wait_group 1;" ::: "memory")
#define CP_WAIT0()  asm volatile("cp.async.wait_group 0;" ::: "memory")

// ---------------------------------------------------------------------------
// Kernel 1: s[b][ci] = style[b]·modW[ci]/sqrt(512) + bias[ci]
// ---------------------------------------------------------------------------
__global__ void k_style(const float* __restrict__ style,
                        const float* __restrict__ modw,
                        const float* __restrict__ modb) {
    int b = blockIdx.x;
    int ci = threadIdx.x;
    __shared__ __align__(16) float ss[CIN];
    ss[ci] = style[b * CIN + ci];
    __syncthreads();
    const float4* row = reinterpret_cast<const float4*>(modw + ci * CIN);
    const float4* s4p = reinterpret_cast<const float4*>(ss);
    float acc = 0.f;
#pragma unroll 4
    for (int k = 0; k < CIN / 4; k++) {
        float4 m = row[k];
        float4 s4 = s4p[k];
        acc += m.x * s4.x + m.y * s4.y + m.z * s4.z + m.w * s4.w;
    }
    g_s[b * CIN + ci] = acc * 0.044194173824159216f + modb[ci];
}

// ---------------------------------------------------------------------------
// Kernel 2 (fused): one weight pass produces BOTH g_wtT and g_demod.
// Block = co. sw[] staged once; demod q computed from sw (smem, not global).
// ---------------------------------------------------------------------------
__global__ void __launch_bounds__(256) k_wd(const float* __restrict__ weight) {
    int co = blockIdx.x;
    int tid = threadIdx.x;
    __shared__ float sw[CIN * 9];
    __shared__ float sred[8][8];
    for (int e = tid; e < CIN * 9; e += 256) sw[e] = weight[co * CIN * 9 + e];
    __syncthreads();
    // ---- wtT
    for (int e = tid; e < CIN * 9; e += 256) {
        int tap = e >> 9, ci = e & 511;
        g_wtT[(tap * COUT + co) * CIN + ci] =
            __float2half_rn(0.014731391274719739f * sw[ci * 9 + tap]);
    }
    // ---- demod (identical math/order to round-15 k_demod, weights from smem)
    float part[B];
#pragma unroll
    for (int b = 0; b < B; b++) part[b] = 0.f;
    for (int cc = 0; cc < 2; cc++) {
        int ci = tid + cc * 256;
        float q = 0.f;
#pragma unroll
        for (int k = 0; k < 9; k++) { float w = sw[ci * 9 + k]; q += w * w; }
#pragma unroll
        for (int b = 0; b < B; b++) {
            float s = g_s[b * CIN + ci];
            part[b] += q * s * s;
        }
    }
#pragma unroll
    for (int b = 0; b < B; b++) {
#pragma unroll
        for (int o = 16; o; o >>= 1)
            part[b] += __shfl_xor_sync(0xffffffffu, part[b], o);
    }
    if ((tid & 31) == 0) {
#pragma unroll
        for (int b = 0; b < B; b++) sred[b][tid >> 5] = part[b];
    }
    __syncthreads();
    if (tid < B) {
        float s = 0.f;
#pragma unroll
        for (int w = 0; w < 8; w++) s += sred[tid][w];
        const float sc2 = 0.014731391274719739f * 0.014731391274719739f;
        g_demod[tid * COUT + co] = rsqrtf(sc2 * s + 1e-8f);
    }
}

// ---------------------------------------------------------------------------
// Kernel 3 (merged): halo zeroing (bx < 2080) + xsT transpose (rest).
// xsT: g_xsT[b][y+1][x+1][ci] = half(x[b][ci][y][x] * s[b][ci]), 128-ci slices.
// ---------------------------------------------------------------------------
__global__ void __launch_bounds__(256, 6) k_prep(const float* __restrict__ x) {
    int bx = blockIdx.x;
    int tid = threadIdx.x;
    if (bx < 2080) {
        // ---- halo: zero y1 in {0,65} or x1 in {0,65}
        int b = bx / 260, px = bx - b * 260;
        int y1, x1;
        if (px < 66)       { y1 = 0;  x1 = px; }
        else if (px < 132) { y1 = 65; x1 = px - 66; }
        else if (px < 196) { y1 = px - 132 + 1; x1 = 0; }
        else               { y1 = px - 196 + 1; x1 = 65; }
        reinterpret_cast<__half2*>(
            g_xsT + ((size_t)(b * 66 + y1) * 66 + x1) * CIN)[tid] =
            __floats2half2_rn(0.f, 0.f);
        return;
    }
    // ---- xsT
    __shared__ float t[32][65];
    int e0 = bx - 2080;                       // 2048 blocks: y(64) b(8) slice(4)
    int y = e0 & 63, b = (e0 >> 6) & 7;
    int cib = (e0 >> 9) * 128;
    const float* xb = x + (size_t)b * CIN * H * W + y * W;
    __half* ob = g_xsT + ((size_t)(b * 66 + y + 1) * 66 + 1) * CIN;
    for (int cc = 0; cc < 4; cc++) {
        int ci0 = cib + cc * 32;
        __syncthreads();
#pragma unroll
        for (int k = 0; k < 8; k++) {
            int e = tid + k * 256;
            int ci = e >> 6, xc = e & 63;
            float s = g_s[b * CIN + ci0 + ci];
            t[ci][xc] = xb[(ci0 + ci) * H * W + xc] * s;
        }
        __syncthreads();
#pragma unroll
        for (int k = 0; k < 4; k++) {
            int e = tid + k * 256;
            int xc = e >> 4, cp = e & 15;
            __half2 h = __floats2half2_rn(t[cp * 2][xc], t[cp * 2 + 1][xc]);
            *(reinterpret_cast<__half2*>(ob + (size_t)xc * CIN + ci0) + cp) = h;
        }
    }
}

// ---------------------------------------------------------------------------
// Kernel 4: conv — FAT WARP config (round-16 proven). One launch, 4 parities.
// CTA: 128 co x 128 px, 128 threads (4 warps: 2wm x 2wn, 64co x 64px each).
// 3-stage cp.async pipeline, one __syncthreads per 64-ci chunk. 2 CTA/SM.
// ---------------------------------------------------------------------------
#define SM_US   0
#define SM_VS   512
#define SM_UE   1024
#define SM_BUF  2048
#define SM_DYN  100352

__global__ void __launch_bounds__(128, 2) k_conv() {
    extern __shared__ __align__(1024) char smem[];
    const uint32_t sb = smem_u32(smem);
    int* us = (int*)(smem + SM_US);
    int* vs = (int*)(smem + SM_VS);
    int* ue = (int*)(smem + SM_UE);

    const int tid = threadIdx.x;
    const int lane = tid & 31, warp = tid >> 5;
    const int g = lane >> 2, tg = lane & 3;
    const int wm = warp >> 1, wn = warp & 1;
    const int cobase = blockIdx.y * 128;
    const int b = blockIdx.z;

    int bx = blockIdx.x;
    int py, px, xt;
    if (bx < 34)       { py = 0; px = 0; xt = bx; }
    else if (bx < 67)  { py = 0; px = 1; xt = bx - 34; }
    else if (bx < 100) { py = 1; px = 0; xt = bx - 67; }
    else               { py = 1; px = 1; xt = bx - 100; }
    const int U = 65 - py, V = 65 - px;
    const int NPIX = U * V;
    const int nky = 2 - py, nkx = 2 - px;
    const int NC = nky * nkx * 8;
    const int n0 = xt * 128;

    {
        int p = n0 + tid;
        int u = p / V, v = p - u * V;
        bool ok = (p < NPIX);
        us[tid] = ok ? u : 0;
        vs[tid] = ok ? v : 0;
        ue[tid] = ok ? u : -1;
    }
    __syncthreads();

    const __half* xb = g_xsT + (size_t)b * 66 * 66 * CIN;

    auto issue = [&](int gidx) {
        const int t = gidx >> 3;
        const int ci0 = (gidx & 7) * 64;
        const int iy = (nkx == 2) ? (t >> 1) : t;
        const int ix = t - iy * nkx;
        const int ky = (py == 0) ? iy * 2 : 1;
        const int kx = (px == 0) ? ix * 2 : 1;
        const int dy = (py == 0) ? iy : 0;
        const int dx = (px == 0) ? ix : 0;
        const int bufi = gidx - (gidx / 3) * 3;
        const uint32_t Ab = sb + SM_BUF + bufi * 32768;
        const uint32_t Bb = Ab + 16384;
        const __half* wt = g_wtT + (ky * 3 + kx) * COUT * CIN + ci0;
#pragma unroll
        for (int k = 0; k < 8; k++) {
            int f = tid + k * 128;
            int co = f >> 3, q = f & 7;
            const __half* src = wt + (size_t)(cobase + co) * CIN + q * 8;
            CP_ASYNC16(Ab + sw128(co * 128 + q * 16), src);
        }
#pragma unroll
        for (int k = 0; k < 8; k++) {
            int f = tid + k * 128;
            int j = f >> 3, q = f & 7;
            int y1 = us[j] + 1 - dy, x1 = vs[j] + 1 - dx;
            const __half* src = xb + ((size_t)(y1 * 66 + x1)) * CIN + ci0 + q * 8;
            CP_ASYNC16(Bb + sw128(j * 128 + q * 16), src);
        }
        CP_COMMIT();
    };

    float acc[4][8][4];
#pragma unroll
    for (int mi = 0; mi < 4; mi++)
#pragma unroll
        for (int nt = 0; nt < 8; nt++)
#pragma unroll
            for (int r = 0; r < 4; r++) acc[mi][nt][r] = 0.f;

    issue(0);
    issue(1);

    const int arow = wm * 64 + (lane & 15);
    const int acolb = (lane >> 4) * 16;
    const int brow = wn * 64 + ((lane >> 4) << 3) + (lane & 7);
    const int bcolb = ((lane >> 3) & 1) * 16;

#pragma unroll 1
    for (int c = 0; c < NC; c++) {
        if (c == NC - 1) { CP_WAIT0(); } else { CP_WAIT1(); }
        __syncthreads();
        if (c + 2 < NC) issue(c + 2);
        const int bufi = c - (c / 3) * 3;
        const uint32_t Ab = sb + SM_BUF + bufi * 32768;
        const uint32_t Bb = Ab + 16384;
#pragma unroll
        for (int ks = 0; ks < 4; ks++) {
            uint32_t a[4][4], bb[8][2];
#pragma unroll
            for (int mi = 0; mi < 4; mi++) {
                uint32_t addr = Ab + sw128((arow + mi * 16) * 128 + acolb + ks * 32);
                asm volatile(
                    "ldmatrix.sync.aligned.m8n8.x4.shared.b16 {%0,%1,%2,%3}, [%4];"
                    : "=r"(a[mi][0]), "=r"(a[mi][1]), "=r"(a[mi][2]), "=r"(a[mi][3])
                    : "r"(addr) : "memory");
            }
#pragma unroll
            for (int ntp = 0; ntp < 4; ntp++) {
                uint32_t addr = Bb + sw128((brow + ntp * 16) * 128 + bcolb + ks * 32);
                uint32_t r0, r1, r2, r3;
                asm volatile(
                    "ldmatrix.sync.aligned.m8n8.x4.shared.b16 {%0,%1,%2,%3}, [%4];"
                    : "=r"(r0), "=r"(r1), "=r"(r2), "=r"(r3)
                    : "r"(addr) : "memory");
                bb[ntp * 2][0] = r0;     bb[ntp * 2][1] = r1;
                bb[ntp * 2 + 1][0] = r2; bb[ntp * 2 + 1][1] = r3;
            }
#pragma unroll
            for (int mi = 0; mi < 4; mi++)
#pragma unroll
                for (int nt = 0; nt < 8; nt++) {
                    asm volatile(
                        "mma.sync.aligned.m16n8k16.row.col.f32.f16.f16.f32 "
                        "{%0,%1,%2,%3}, {%4,%5,%6,%7}, {%8,%9}, {%0,%1,%2,%3};"
                        : "+f"(acc[mi][nt][0]), "+f"(acc[mi][nt][1]),
                          "+f"(acc[mi][nt][2]), "+f"(acc[mi][nt][3])
                        : "r"(a[mi][0]), "r"(a[mi][1]), "r"(a[mi][2]),
                          "r"(a[mi][3]), "r"(bb[nt][0]), "r"(bb[nt][1]));
                }
        }
    }

    __half* plane = g_midp[py * 2 + px];
#pragma unroll
    for (int mi = 0; mi < 4; mi++) {
        int r0 = cobase + wm * 64 + mi * 16 + g;
        float d0 = g_demod[b * COUT + r0];
        float d1 = g_demod[b * COUT + r0 + 8];
        __half* p0 = plane + (size_t)(b * COUT + r0) * 65 * 68;
        __half* p1 = plane + (size_t)(b * COUT + r0 + 8) * 65 * 68;
#pragma unroll
        for (int nt = 0; nt < 8; nt++) {
            int j = wn * 64 + nt * 8 + tg * 2;
            int u0 = ue[j], u1 = ue[j + 1];
            int v0 = vs[j], v1 = vs[j + 1];
            if (u0 >= 0 && u1 == u0 && v1 == v0 + 1 && (v0 & 1) == 0) {
                __half2 h0 = __floats2half2_rn(acc[mi][nt][0] * d0,
                                               acc[mi][nt][1] * d0);
                __half2 h1 = __floats2half2_rn(acc[mi][nt][2] * d1,
                                               acc[mi][nt][3] * d1);
                *reinterpret_cast<__half2*>(p0 + u0 * 68 + v0) = h0;
                *reinterpret_cast<__half2*>(p1 + u0 * 68 + v0) = h1;
            } else {
                if (u0 >= 0) {
                    p0[u0 * 68 + v0] = __float2half_rn(acc[mi][nt][0] * d0);
                    p1[u0 * 68 + v0] = __float2half_rn(acc[mi][nt][2] * d1);
                }
                if (u1 >= 0) {
                    p0[u1 * 68 + v1] = __float2half_rn(acc[mi][nt][1] * d0);
                    p1[u1 * 68 + v1] = __float2half_rn(acc[mi][nt][3] * d1);
                }
            }
        }
    }
}

// ---------------------------------------------------------------------------
// Kernel 5: plane-resident blur, X-pair per thread (round-15 proven).
// ---------------------------------------------------------------------------
#define PLN 4420  // 65*68 halves per plane

__global__ void __launch_bounds__(256) k_blur(float* __restrict__ out) {
    int bc = blockIdx.x;
    __shared__ __align__(16) __half sm[8 + 4 * PLN];
    const int tid = threadIdx.x;

    for (int e = tid; e < 4 * 65 * 17; e += 256) {
        int p = e / (65 * 17);
        int rem = e - p * 65 * 17;
        int r = rem / 17, c4 = rem - r * 17;
        uint2 val = *reinterpret_cast<const uint2*>(
            g_midp[p] + (size_t)bc * PLN + r * 68 + c4 * 4);
        *reinterpret_cast<uint2*>(sm + 8 + p * PLN + r * 68 + c4 * 4) = val;
    }
    if (tid < 8) sm[tid] = __float2half(0.f);
    __syncthreads();
#pragma unroll
    for (int p = 0; p < 4; p++) {
        int Vp = 65 - (p & 1);
        int nc = 68 - Vp;
        for (int e = tid; e < 65 * nc; e += 256) {
            int rr = e / nc, cc = e - rr * nc;
            sm[8 + p * PLN + rr * 68 + Vp + cc] = __float2half(0.f);
        }
        if (p >> 1) {
            for (int e = tid; e < 68; e += 256)
                sm[8 + p * PLN + 64 * 68 + e] = __float2half(0.f);
        }
    }
    __syncthreads();

    const int v = tid & 63, strip = tid >> 6;
    const __half* sp = sm + 8;
    const __half* pE0 = sp;
    const __half* pO0 = sp + PLN;
    const __half* pE1 = sp + 2 * PLN;
    const __half* pO1 = sp + 3 * PLN;

    auto HS2 = [&](const __half* E, const __half* O, int r,
                   float& h0, float& h1) {
        const __half* Er = E + r * 68;
        const __half* Or = O + r * 68;
        float e0 = __half2float(Er[v]);
        float e1 = __half2float(Er[v + 1]);
        float om = __half2float(Or[v - 1]);
        float o0 = __half2float(Or[v]);
        float o1 = __half2float(Or[v + 1]);
        h0 = om + 3.f * e0 + 3.f * o0 + e1;
        h1 = e0 + 3.f * o0 + 3.f * e1 + o1;
    };

    const int u0 = strip * 16;
    float hoP0, hoP1;
    if (u0 == 0) { hoP0 = 0.f; hoP1 = 0.f; }
    else HS2(pE1, pO1, u0 - 1, hoP0, hoP1);
    float heC0, heC1, hoC0, hoC1;
    HS2(pE0, pO0, u0, heC0, heC1);
    HS2(pE1, pO1, u0, hoC0, hoC1);

    float* ob = out + (size_t)bc * 16384 + 2 * v;
#pragma unroll 4
    for (int u = u0; u < u0 + 16; u++) {
        float heN0, heN1, hoN0, hoN1;
        HS2(pE0, pO0, u + 1, heN0, heN1);
        HS2(pE1, pO1, u + 1, hoN0, hoN1);
        float2 r0, r1;
        r0.x = (hoP0 + 3.f * heC0 + 3.f * hoC0 + heN0) * (1.f / 16.f);
        r0.y = (hoP1 + 3.f * heC1 + 3.f * hoC1 + heN1) * (1.f / 16.f);
        r1.x = (heC0 + 3.f * hoC0 + 3.f * heN0 + hoN0) * (1.f / 16.f);
        r1.y = (heC1 + 3.f * hoC1 + 3.f * heN1 + hoN1) * (1.f / 16.f);
        *reinterpret_cast<float2*>(ob + (2 * u) * 128) = r0;
        *reinterpret_cast<float2*>(ob + (2 * u + 1) * 128) = r1;
        hoP0 = hoC0; hoP1 = hoC1;
        heC0 = heN0; heC1 = heN1;
        hoC0 = hoN0; hoC1 = hoN1;
    }
}

// ---------------------------------------------------------------------------
extern "C" void kernel_launch(void* const* d_in, const int* in_sizes, int n_in,
                              void* d_out, int out_size) {
    const float* input  = (const float*)d_in[0];
    const float* style  = (const float*)d_in[1];
    const float* weight = (const float*)d_in[2];
    const float* modw   = (const float*)d_in[3];
    const float* modb   = (const float*)d_in[4];
    float* out = (float*)d_out;

    cudaFuncSetAttribute(k_conv, cudaFuncAttributeMaxDynamicSharedMemorySize, SM_DYN);

    k_style<<<B, CIN>>>(style, modw, modb);
    k_wd<<<COUT, 256>>>(weight);
    k_prep<<<2080 + 2048, 256>>>(input);
    k_conv<<<dim3(132, 2, B), 128, SM_DYN>>>();
    k_blur<<<B * COUT, 256>>>(out);
}